// round 15
// baseline (speedup 1.0000x reference)
#include <cuda_runtime.h>
#include <cuda_bf16.h>
#include <math.h>
#include <stdint.h>

#define TT   512
#define BB   64
#define HH   512
#define LL   2
#define NBLK 128          // recurrence grid (1 CTA/SM, all co-resident)

typedef unsigned long long ull;

// ---------------- scratch (__device__ globals; allocation-free) ----------------
__device__ float g_gx[3][TT * BB * HH];     // gate-x planes (r,z,n) for current layer
__device__ float g_xc[TT * BB * HH];        // tf32-rounded A for current layer GEMM
__device__ float g_wc[3][HH * HH];          // tf32-rounded input weights (current layer)
__device__ float g_ht[2][HH * BB];          // hidden state, k-major [k][b] (tf32-rounded)
__device__ unsigned int g_hflag[NBLK * 32]; // producer: h for step t stored (value t+1)
__device__ unsigned int g_rflag[NBLK * 32]; // consumer: step-t reads complete (value t+1)

// tf32 round-to-nearest of an fp32 (bits usable by mma.tf32)
__device__ __forceinline__ float tf32r(float x) {
    uint32_t y;
    asm("cvt.rna.tf32.f32 %0, %1;" : "=r"(y) : "f"(x));
    return __uint_as_float(y);
}

__device__ __forceinline__ void mma_tf32(float c[4], const uint32_t a[4],
                                         const uint32_t b[2]) {
    asm volatile(
        "mma.sync.aligned.m16n8k8.row.col.f32.tf32.tf32.f32 "
        "{%0,%1,%2,%3}, {%4,%5,%6,%7}, {%8,%9}, {%0,%1,%2,%3};"
        : "+f"(c[0]), "+f"(c[1]), "+f"(c[2]), "+f"(c[3])
        : "r"(a[0]), "r"(a[1]), "r"(a[2]), "r"(a[3]), "r"(b[0]), "r"(b[1]));
}

// cp.async 16B (L2-cached) + group control
__device__ __forceinline__ void cpa16(uint32_t smem, const void* g) {
    asm volatile("cp.async.cg.shared.global [%0], [%1], 16;"
                 :: "r"(smem), "l"(g) : "memory");
}
#define CP_COMMIT()  asm volatile("cp.async.commit_group;" ::: "memory")
#define CP_WAIT_1()  asm volatile("cp.async.wait_group 1;" ::: "memory")
#define CP_WAIT_0()  asm volatile("cp.async.wait_group 0;" ::: "memory")

__device__ __forceinline__ void flag_release(unsigned int* p, unsigned v) {
    asm volatile("st.global.release.gpu.u32 [%0], %1;" :: "l"(p), "r"(v) : "memory");
}
__device__ __forceinline__ unsigned flag_acquire(const unsigned int* p) {
    unsigned v;
    asm volatile("ld.global.acquire.gpu.u32 %0, [%1];" : "=r"(v) : "l"(p) : "memory");
    return v;
}

// ---------------- operand pre-conversion ------------------------------------------
__global__ __launch_bounds__(256) void conv_x(const float* __restrict__ x) {
    const int i = blockIdx.x * 256 + threadIdx.x;     // float4 index
    float4 v = *(const float4*)(x + (size_t)i * 4);
    v.x = tf32r(v.x); v.y = tf32r(v.y); v.z = tf32r(v.z); v.w = tf32r(v.w);
    *(float4*)(g_xc + (size_t)i * 4) = v;
}

__global__ __launch_bounds__(256) void conv_w(const float* __restrict__ w0,
                                              const float* __restrict__ w1,
                                              const float* __restrict__ w2) {
    const int i = blockIdx.x * 256 + threadIdx.x;     // float4 index, < 196608
    const int m = i >> 16;                            // 65536 float4 per matrix
    const int rem = i & 65535;
    const float* src = (m == 0) ? w0 : ((m == 1) ? w1 : w2);
    float4 v = *(const float4*)(src + (size_t)rem * 4);
    v.x = tf32r(v.x); v.y = tf32r(v.y); v.z = tf32r(v.z); v.w = tf32r(v.w);
    *(float4*)(g_wc[m] + (size_t)rem * 4) = v;
}

// ---------------- h0 transpose + flag reset ---------------------------------------
__global__ __launch_bounds__(256) void transpose_h0(const float* __restrict__ h0) {
    const int i = blockIdx.x * 256 + threadIdx.x;   // 0..32767
    const int k = i >> 6;
    const int b = i & 63;
    g_ht[1][i] = tf32r(h0[(size_t)b * HH + k]);
    if (i < NBLK) { g_hflag[i * 32] = 0; g_rflag[i * 32] = 0; }
}

// ---------------- input GEMM (tensor cores, tf32, cp.async 3-stage) ---------------
// C = g_xc(M,512) * g_wc[gate](512,512) + bias ; BM=128, BN=128, BK=32,
// 256 thr (8 warps), warp tile 64x32 (m16n8k8 x 4m x 4n). blockIdx.z = gate.
#define APITCH 36
#define BPITCH 136
#define A_STG (128 * APITCH)                 // 4608 floats
#define B_STG (32 * BPITCH)                  // 4352 floats
#define GEMM_SMEM_FLOATS (3 * A_STG + 3 * B_STG)

__global__ __launch_bounds__(256) void gemm_xw_mma(const float* __restrict__ bias0,
                                                   const float* __restrict__ bias1,
                                                   const float* __restrict__ bias2) {
    extern __shared__ float gsm[];
    const int gate = blockIdx.z;
    const float* A    = g_xc;
    const float* W    = g_wc[gate];
    const float* bias = (gate == 0) ? bias0 : ((gate == 1) ? bias1 : bias2);

    const int bm = blockIdx.x * 128;
    const int bn = blockIdx.y * 128;
    const int tid = threadIdx.x;
    const int lane = tid & 31;
    const int wid = tid >> 5;
    const int warp_m = wid >> 2;              // 0..1
    const int warp_n = wid & 3;               // 0..3

    const uint32_t sm_u32 = (uint32_t)__cvta_generic_to_shared(gsm);

    float acc[4][4][4];
#pragma unroll
    for (int mt = 0; mt < 4; mt++)
#pragma unroll
        for (int nt = 0; nt < 4; nt++)
#pragma unroll
            for (int i = 0; i < 4; i++) acc[mt][nt][i] = 0.f;

#define GSTAGE(s, kt32)                                                          \
    {                                                                            \
        _Pragma("unroll")                                                        \
        for (int i = 0; i < 4; i++) {                                            \
            const int idx = i * 256 + tid;                                       \
            const int arow = idx >> 3;                                           \
            const int kq = idx & 7;                                              \
            cpa16(sm_u32 + (uint32_t)((s) * A_STG + arow * APITCH + kq * 4) * 4u,\
                  A + (size_t)(bm + arow) * HH + (kt32) + kq * 4);               \
        }                                                                        \
        _Pragma("unroll")                                                        \
        for (int i = 0; i < 4; i++) {                                            \
            const int idx = i * 256 + tid;                                       \
            const int krow = idx >> 5;                                           \
            const int nq = idx & 31;                                             \
            cpa16(sm_u32 + (uint32_t)(3 * A_STG + (s) * B_STG + krow * BPITCH    \
                                      + nq * 4) * 4u,                            \
                  W + (size_t)((kt32) + krow) * HH + bn + nq * 4);               \
        }                                                                        \
        CP_COMMIT();                                                             \
    }

    GSTAGE(0, 0)
    GSTAGE(1, 32)

    const int r = lane >> 2;
    const int cq = lane & 3;
    const int mrow = warp_m * 64 + r;
    const int nbase = warp_n * 32 + r;

    for (int it = 0; it < 16; it++) {
        const int kt = it * 32;
        if (kt == 480) { CP_WAIT_0(); } else { CP_WAIT_1(); }
        __syncthreads();
        if (kt + 64 < HH) GSTAGE((it + 2) % 3, kt + 64)

        const float* Ab = gsm + (it % 3) * A_STG;
        const float* Bb = gsm + 3 * A_STG + (it % 3) * B_STG;

#pragma unroll
        for (int ks = 0; ks < 4; ks++) {
            const int kk = ks * 8;
            uint32_t af[4][4];
#pragma unroll
            for (int mt = 0; mt < 4; mt++) {
                const int mr = mrow + mt * 16;
                af[mt][0] = __float_as_uint(Ab[mr * APITCH + kk + cq]);
                af[mt][1] = __float_as_uint(Ab[(mr + 8) * APITCH + kk + cq]);
                af[mt][2] = __float_as_uint(Ab[mr * APITCH + kk + cq + 4]);
                af[mt][3] = __float_as_uint(Ab[(mr + 8) * APITCH + kk + cq + 4]);
            }
            uint32_t bf[4][2];
#pragma unroll
            for (int nt = 0; nt < 4; nt++) {
                bf[nt][0] = __float_as_uint(Bb[(kk + cq) * BPITCH + nbase + nt * 8]);
                bf[nt][1] = __float_as_uint(Bb[(kk + cq + 4) * BPITCH + nbase + nt * 8]);
            }
#pragma unroll
            for (int mt = 0; mt < 4; mt++)
#pragma unroll
                for (int nt = 0; nt < 4; nt++)
                    mma_tf32(acc[mt][nt], af[mt], bf[nt]);
        }
        __syncthreads();
    }

    // epilogue
    float* C = g_gx[0] + (size_t)gate * ((size_t)TT * BB * HH);
    const int m0 = bm + warp_m * 64 + r;
    const int n0 = bn + warp_n * 32 + 2 * cq;
#pragma unroll
    for (int nt = 0; nt < 4; nt++) {
        const int col = n0 + nt * 8;
        const float b0 = bias[col];
        const float b1 = bias[col + 1];
#pragma unroll
        for (int mt = 0; mt < 4; mt++) {
            const int row0 = m0 + mt * 16;
            float2 v0 = make_float2(acc[mt][nt][0] + b0, acc[mt][nt][1] + b1);
            float2 v1 = make_float2(acc[mt][nt][2] + b0, acc[mt][nt][3] + b1);
            *(float2*)&C[(size_t)row0 * HH + col] = v0;
            *(float2*)&C[(size_t)(row0 + 8) * HH + col] = v1;
        }
    }
#undef GSTAGE
}

// ---------------- persistent recurrence (tf32 mma, fine-grained flags) ------------
// 128 CTAs x 256 threads; grid tiled 4 batch-groups x 32 column-groups.
// CTA owns 16 batches x 16 columns. Warp = 64-k slice.
// Sync protocol (replaces the global barrier):
//   RAW: warp w needs h rows k in [64w,64w+64) of batch group bg -> 4 producers
//        (bg*32 + 4w + 0..3). Lanes 0..3 acquire-poll hflag >= t, then issue
//        cp.async chunks.
//   WAR: each CTA release-posts rflag = t+1 right after its dot reads complete;
//        the h-writer checks all rflag >= t after reduce (latency hidden).
#define HTP  24
#define REDP 52
#define SMEM_FLOATS (HH * HTP + 8 * 16 * REDP)

__global__ __launch_bounds__(256) void gru_recurrence(
    const float* __restrict__ whr, const float* __restrict__ whz,
    const float* __restrict__ whn,
    const float* __restrict__ bhr, const float* __restrict__ bhz,
    const float* __restrict__ bhn,
    float* __restrict__ seq,          // [T,B,H]
    float* __restrict__ finals)       // [B,H]
{
    extern __shared__ float sm[];
    float* ht  = sm;                          // [512][HTP] h slice (k-major, tf32 bits)
    float* red = sm + HH * HTP;               // [8][16][REDP] partials

    const int tid = threadIdx.x;
    const int w   = tid >> 5;                 // warp = 64-k slice (0..7)
    const int lane = tid & 31;
    const int r  = lane >> 2;                 // fragment row group
    const int cq = lane & 3;                  // fragment col group
    const int bg    = blockIdx.x >> 5;        // batch group (0..3)
    const int bbase = bg * 16;
    const int jbase = (blockIdx.x & 31) * 16; // column group

    // activation-phase identity: 256 threads = 16 batches x 16 cols
    const int ab = tid >> 4;                  // local batch 0..15
    const int aj = tid & 15;                  // local col 0..15
    const int jglob = jbase + aj;

    // ---- load W fragments (once, resident all 512 steps) ----
    uint32_t bw[8][6][2];
#pragma unroll
    for (int ks = 0; ks < 8; ks++)
#pragma unroll
        for (int nt = 0; nt < 6; nt++)
#pragma unroll
            for (int e = 0; e < 2; e++) {
                const int g  = nt >> 1;
                const int jh = nt & 1;
                const int k = (w << 6) + ks * 8 + cq + e * 4;
                const float* src = (g == 0) ? whr : ((g == 1) ? whz : whn);
                bw[ks][nt][e] =
                    __float_as_uint(tf32r(src[(size_t)k * HH + jbase + jh * 8 + r]));
            }
    const float bh_r = bhr[jglob];
    const float bh_z = bhz[jglob];
    const float bh_n = bhn[jglob];
    __syncthreads();

    const uint32_t ht_u32 = (uint32_t)__cvta_generic_to_shared(ht);

#define ISSUE_CHUNK(cc)                                                          \
    {                                                                            \
        _Pragma("unroll")                                                        \
        for (int i = 0; i < 4; i++) {                                            \
            const int id = i * 32 + lane;                                        \
            const int row = (w << 6) + (cc) * 32 + (id >> 2);                    \
            const int col4 = id & 3;                                             \
            cpa16(ht_u32 + (uint32_t)(row * HTP + col4 * 4) * 4u,                \
                  src4 + row * 16 + bg * 4 + col4);                              \
        }                                                                        \
        CP_COMMIT();                                                             \
    }

    for (int t = 0; t < TT; t++) {
        // prefetch gate-x (hidden under dot)
        const int gi = (t * BB + bbase + ab) * HH + jglob;
        const float gxr = __ldcs(&g_gx[0][gi]);
        const float gxz = __ldcs(&g_gx[1][gi]);
        const float gxn = __ldcs(&g_gx[2][gi]);

        const float4* src4 = (const float4*)g_ht[(t - 1) & 1];

        // RAW: wait for this warp's 4 producer CTAs to have stored step-(t-1) h
        if (t > 0) {
            if (lane < 4) {
                const int p = (bg << 5) + (w << 2) + lane;
                while (flag_acquire(&g_hflag[p * 32]) < (unsigned)t) { }
            }
            __syncwarp();
        }

        float cacc[6][4];
#pragma unroll
        for (int nt = 0; nt < 6; nt++)
#pragma unroll
            for (int i = 0; i < 4; i++) cacc[nt][i] = 0.f;

        ISSUE_CHUNK(0)
        ISSUE_CHUNK(1)

#pragma unroll
        for (int c = 0; c < 2; c++) {
            if (c == 0) CP_WAIT_1(); else CP_WAIT_0();
            __syncwarp();

#pragma unroll
            for (int ks2 = 0; ks2 < 4; ks2++) {
                const int ks = c * 4 + ks2;
                const int kb = (w << 6) + ks * 8;
                uint32_t a[4];
                const int base = (kb + cq) * HTP + r;
                a[0] = __float_as_uint(ht[base]);
                a[1] = __float_as_uint(ht[base + 8]);
                a[2] = __float_as_uint(ht[base + 4 * HTP]);
                a[3] = __float_as_uint(ht[base + 4 * HTP + 8]);
#pragma unroll
                for (int nt = 0; nt < 6; nt++)
                    mma_tf32(cacc[nt], a, bw[ks][nt]);
            }
        }

        // store partials: red[w][b][n]
        {
            float* rb = red + w * (16 * REDP);
#pragma unroll
            for (int nt = 0; nt < 6; nt++) {
                const int n0 = nt * 8 + 2 * cq;
                *(float2*)&rb[r * REDP + n0] =
                    make_float2(cacc[nt][0], cacc[nt][1]);
                *(float2*)&rb[(r + 8) * REDP + n0] =
                    make_float2(cacc[nt][2], cacc[nt][3]);
            }
        }
        __syncthreads();   // all warps: cp.async complete + partials visible

        // post read-done early: WAR wait below overlaps with reduce
        if (tid == 0) flag_release(&g_rflag[blockIdx.x * 32], (unsigned)(t + 1));

        // ---- reduce over 8 warps + activation (thread = (ab, aj)) ----
        float ar = bh_r, az = bh_z, an = bh_n;
#pragma unroll
        for (int ww = 0; ww < 8; ww++) {
            const float* rb = red + ww * (16 * REDP) + ab * REDP;
            ar += rb[aj];
            az += rb[16 + aj];
            an += rb[32 + aj];
        }

        const float rg = 1.f / (1.f + __expf(-(gxr + ar)));
        const float zg = 1.f / (1.f + __expf(-(gxz + az)));
        const float ng = tanhf(gxn + rg * an);
        const float hp = ht[jglob * HTP + ab];          // h_prev from smem stage
        const float hn_ = (1.f - zg) * ng + zg * hp;

        // WAR: all CTAs must have finished reading the buffer we overwrite
        if (t > 0 && tid < NBLK) {
            while (flag_acquire(&g_rflag[tid * 32]) < (unsigned)t) { }
        }
        __syncthreads();

        const float hq = tf32r(hn_);
        __stcg(&g_ht[t & 1][jglob * BB + bbase + ab], hq);
        __stcg(&g_xc[gi], hq);                          // next layer's A (tf32)
        seq[gi] = hn_;
        if (t == TT - 1) finals[(size_t)(bbase + ab) * HH + jglob] = hn_;

        __syncthreads();   // h stores done block-wide
        if (tid == 0) flag_release(&g_hflag[blockIdx.x * 32], (unsigned)(t + 1));
    }
#undef ISSUE_CHUNK
}

// -------------------------------- launch -----------------------------------------
extern "C" void kernel_launch(void* const* d_in, const int* in_sizes, int n_in,
                              void* d_out, int out_size) {
    const float* x    = (const float*)d_in[0];
    const float* init = (const float*)d_in[1];
    const float* w_ir = (const float*)d_in[2];
    const float* w_hr = (const float*)d_in[3];
    const float* w_iz = (const float*)d_in[4];
    const float* w_hz = (const float*)d_in[5];
    const float* w_in = (const float*)d_in[6];
    const float* w_hn = (const float*)d_in[7];
    const float* b_ir = (const float*)d_in[8];
    const float* b_hr = (const float*)d_in[9];
    const float* b_iz = (const float*)d_in[10];
    const float* b_hz = (const float*)d_in[11];
    const float* b_in = (const float*)d_in[12];
    const float* b_hn = (const float*)d_in[13];

    float* out    = (float*)d_out;
    float* seq    = out;                          // [T,B,H]
    float* finals = out + (size_t)TT * BB * HH;   // [L,B,H]

    const size_t rec_smem = (size_t)SMEM_FLOATS * sizeof(float);
    cudaFuncSetAttribute(gru_recurrence,
                         cudaFuncAttributeMaxDynamicSharedMemorySize,
                         (int)rec_smem);
    const size_t gemm_smem = (size_t)GEMM_SMEM_FLOATS * sizeof(float);
    cudaFuncSetAttribute(gemm_xw_mma,
                         cudaFuncAttributeMaxDynamicSharedMemorySize,
                         (int)gemm_smem);

    dim3 ggrid(TT * BB / 128, HH / 128, 3);       // 256 x 4 x 3

    conv_x<<<TT * BB * HH / 1024, 256>>>(x);      // layer-0 A (tf32)

    for (int l = 0; l < LL; l++) {
        const size_t wo = (size_t)l * HH * HH;
        const size_t bo = (size_t)l * HH;

        conv_w<<<3 * HH * HH / 1024, 256>>>(w_ir + wo, w_iz + wo, w_in + wo);

        gemm_xw_mma<<<ggrid, 256, gemm_smem>>>(b_ir + bo, b_iz + bo, b_in + bo);

        transpose_h0<<<HH * BB / 256, 256>>>(init + (size_t)l * BB * HH);

        gru_recurrence<<<NBLK, 256, rec_smem>>>(
            w_hr + wo, w_hz + wo, w_hn + wo,
            b_hr + bo, b_hz + bo, b_hn + bo,
            seq,
            finals + (size_t)l * BB * HH);
    }
}

// round 16
// speedup vs baseline: 1.1060x; 1.1060x over previous
#include <cuda_runtime.h>
#include <cuda_bf16.h>
#include <math.h>
#include <stdint.h>

#define TT   512
#define BB   64
#define HH   512
#define LL   2
#define NBLK 128          // recurrence grid (1 CTA/SM, all co-resident)

typedef unsigned long long ull;

// ---------------- scratch (__device__ globals; allocation-free) ----------------
__device__ float g_gx[3][TT * BB * HH];     // gate-x planes (r,z,n) for current layer
__device__ float g_xc[TT * BB * HH];        // tf32-rounded A for current layer GEMM
__device__ float g_wc[LL][3][HH * HH];      // tf32-rounded input weights (both layers)
__device__ float g_ht[2][HH * BB];          // hidden state, k-major [k][b] (tf32-rounded)
__device__ unsigned int g_flags[NBLK * 32]; // per-CTA barrier flags, 128B stride

// tf32 round-to-nearest of an fp32 (bits usable by mma.tf32)
__device__ __forceinline__ float tf32r(float x) {
    uint32_t y;
    asm("cvt.rna.tf32.f32 %0, %1;" : "=r"(y) : "f"(x));
    return __uint_as_float(y);
}

__device__ __forceinline__ void mma_tf32(float c[4], const uint32_t a[4],
                                         const uint32_t b[2]) {
    asm volatile(
        "mma.sync.aligned.m16n8k8.row.col.f32.tf32.tf32.f32 "
        "{%0,%1,%2,%3}, {%4,%5,%6,%7}, {%8,%9}, {%0,%1,%2,%3};"
        : "+f"(c[0]), "+f"(c[1]), "+f"(c[2]), "+f"(c[3])
        : "r"(a[0]), "r"(a[1]), "r"(a[2]), "r"(a[3]), "r"(b[0]), "r"(b[1]));
}

// cp.async 16B (L2-cached) + group control
__device__ __forceinline__ void cpa16(uint32_t smem, const void* g) {
    asm volatile("cp.async.cg.shared.global [%0], [%1], 16;"
                 :: "r"(smem), "l"(g) : "memory");
}
#define CP_COMMIT()  asm volatile("cp.async.commit_group;" ::: "memory")
#define CP_WAIT_1()  asm volatile("cp.async.wait_group 1;" ::: "memory")
#define CP_WAIT_0()  asm volatile("cp.async.wait_group 0;" ::: "memory")

// ---------------- operand pre-conversion ------------------------------------------
__global__ __launch_bounds__(256) void conv_x(const float* __restrict__ x) {
    const int i = blockIdx.x * 256 + threadIdx.x;     // float4 index
    float4 v = *(const float4*)(x + (size_t)i * 4);
    v.x = tf32r(v.x); v.y = tf32r(v.y); v.z = tf32r(v.z); v.w = tf32r(v.w);
    *(float4*)(g_xc + (size_t)i * 4) = v;
}

// both layers, all 3 gates in one launch (6 matrices)
__global__ __launch_bounds__(256) void conv_w(const float* __restrict__ w0,
                                              const float* __restrict__ w1,
                                              const float* __restrict__ w2) {
    const int i = blockIdx.x * 256 + threadIdx.x;     // float4 index, < 393216
    const int m = i >> 16;                            // 0..5
    const int layer = m >> 1 >= 3 ? 1 : (m / 3);      // m in [0,3) -> 0; [3,6) -> 1
    const int gate  = m - layer * 3;
    const int rem = i & 65535;
    const float* base = (gate == 0) ? w0 : ((gate == 1) ? w1 : w2);
    const float* src = base + (size_t)layer * HH * HH;
    float4 v = *(const float4*)(src + (size_t)rem * 4);
    v.x = tf32r(v.x); v.y = tf32r(v.y); v.z = tf32r(v.z); v.w = tf32r(v.w);
    *(float4*)(g_wc[layer][gate] + (size_t)rem * 4) = v;
}

// ---------------- h0 transpose + barrier-flag reset ------------------------------
__global__ __launch_bounds__(256) void transpose_h0(const float* __restrict__ h0) {
    const int i = blockIdx.x * 256 + threadIdx.x;   // 0..32767
    const int k = i >> 6;
    const int b = i & 63;
    g_ht[1][i] = tf32r(h0[(size_t)b * HH + k]);
    if (i < NBLK) g_flags[i * 32] = 0;              // reset barrier flags per layer
}

// ---------------- input GEMM (tensor cores, tf32, cp.async 3-stage) ---------------
// C = g_xc(M,512) * g_wc[layer][gate](512,512) + bias ; BM=128, BN=128, BK=32,
// 256 thr (8 warps), warp tile 64x32 (m16n8k8 x 4m x 4n). blockIdx.z = gate.
// ONE __syncthreads per k-iter: the top-of-iter sync (after wait_group) both
// publishes stage it and proves all threads finished reading stage it-1 (the
// buffer GSTAGE(it+2) overwrites).
#define APITCH 36
#define BPITCH 136
#define A_STG (128 * APITCH)                 // 4608 floats
#define B_STG (32 * BPITCH)                  // 4352 floats
#define GEMM_SMEM_FLOATS (3 * A_STG + 3 * B_STG)

__global__ __launch_bounds__(256) void gemm_xw_mma(int layer,
                                                   const float* __restrict__ bias0,
                                                   const float* __restrict__ bias1,
                                                   const float* __restrict__ bias2) {
    extern __shared__ float gsm[];
    const int gate = blockIdx.z;
    const float* A    = g_xc;
    const float* W    = g_wc[layer][gate];
    const float* bias = (gate == 0) ? bias0 : ((gate == 1) ? bias1 : bias2);

    const int bm = blockIdx.x * 128;
    const int bn = blockIdx.y * 128;
    const int tid = threadIdx.x;
    const int lane = tid & 31;
    const int wid = tid >> 5;
    const int warp_m = wid >> 2;              // 0..1
    const int warp_n = wid & 3;               // 0..3

    const uint32_t sm_u32 = (uint32_t)__cvta_generic_to_shared(gsm);

    float acc[4][4][4];
#pragma unroll
    for (int mt = 0; mt < 4; mt++)
#pragma unroll
        for (int nt = 0; nt < 4; nt++)
#pragma unroll
            for (int i = 0; i < 4; i++) acc[mt][nt][i] = 0.f;

#define GSTAGE(s, kt32)                                                          \
    {                                                                            \
        _Pragma("unroll")                                                        \
        for (int i = 0; i < 4; i++) {                                            \
            const int idx = i * 256 + tid;                                       \
            const int arow = idx >> 3;                                           \
            const int kq = idx & 7;                                              \
            cpa16(sm_u32 + (uint32_t)((s) * A_STG + arow * APITCH + kq * 4) * 4u,\
                  A + (size_t)(bm + arow) * HH + (kt32) + kq * 4);               \
        }                                                                        \
        _Pragma("unroll")                                                        \
        for (int i = 0; i < 4; i++) {                                            \
            const int idx = i * 256 + tid;                                       \
            const int krow = idx >> 5;                                           \
            const int nq = idx & 31;                                             \
            cpa16(sm_u32 + (uint32_t)(3 * A_STG + (s) * B_STG + krow * BPITCH    \
                                      + nq * 4) * 4u,                            \
                  W + (size_t)((kt32) + krow) * HH + bn + nq * 4);               \
        }                                                                        \
        CP_COMMIT();                                                             \
    }

    GSTAGE(0, 0)
    GSTAGE(1, 32)

    const int r = lane >> 2;
    const int cq = lane & 3;
    const int mrow = warp_m * 64 + r;
    const int nbase = warp_n * 32 + r;

    for (int it = 0; it < 16; it++) {
        const int kt = it * 32;
        if (kt == 480) { CP_WAIT_0(); } else { CP_WAIT_1(); }
        __syncthreads();
        if (kt + 64 < HH) GSTAGE((it + 2) % 3, kt + 64)

        const float* Ab = gsm + (it % 3) * A_STG;
        const float* Bb = gsm + 3 * A_STG + (it % 3) * B_STG;

#pragma unroll
        for (int ks = 0; ks < 4; ks++) {
            const int kk = ks * 8;
            uint32_t af[4][4];
#pragma unroll
            for (int mt = 0; mt < 4; mt++) {
                const int mr = mrow + mt * 16;
                af[mt][0] = __float_as_uint(Ab[mr * APITCH + kk + cq]);
                af[mt][1] = __float_as_uint(Ab[(mr + 8) * APITCH + kk + cq]);
                af[mt][2] = __float_as_uint(Ab[mr * APITCH + kk + cq + 4]);
                af[mt][3] = __float_as_uint(Ab[(mr + 8) * APITCH + kk + cq + 4]);
            }
            uint32_t bf[4][2];
#pragma unroll
            for (int nt = 0; nt < 4; nt++) {
                bf[nt][0] = __float_as_uint(Bb[(kk + cq) * BPITCH + nbase + nt * 8]);
                bf[nt][1] = __float_as_uint(Bb[(kk + cq + 4) * BPITCH + nbase + nt * 8]);
            }
#pragma unroll
            for (int mt = 0; mt < 4; mt++)
#pragma unroll
                for (int nt = 0; nt < 4; nt++)
                    mma_tf32(acc[mt][nt], af[mt], bf[nt]);
        }
    }

    // epilogue
    float* C = g_gx[0] + (size_t)gate * ((size_t)TT * BB * HH);
    const int m0 = bm + warp_m * 64 + r;
    const int n0 = bn + warp_n * 32 + 2 * cq;
#pragma unroll
    for (int nt = 0; nt < 4; nt++) {
        const int col = n0 + nt * 8;
        const float b0 = bias[col];
        const float b1 = bias[col + 1];
#pragma unroll
        for (int mt = 0; mt < 4; mt++) {
            const int row0 = m0 + mt * 16;
            float2 v0 = make_float2(acc[mt][nt][0] + b0, acc[mt][nt][1] + b1);
            float2 v1 = make_float2(acc[mt][nt][2] + b0, acc[mt][nt][3] + b1);
            *(float2*)&C[(size_t)row0 * HH + col] = v0;
            *(float2*)&C[(size_t)(row0 + 8) * HH + col] = v1;
        }
    }
#undef GSTAGE
}

// ---------------- flag-based grid barrier ----------------------------------------
__device__ __forceinline__ void grid_sync_flags(int target) {
    __syncthreads();
    if (threadIdx.x == 0) {
        asm volatile("st.global.release.gpu.u32 [%0], %1;"
                     :: "l"(&g_flags[blockIdx.x * 32]), "r"((unsigned)target)
                     : "memory");
    }
    if (threadIdx.x < NBLK) {
        unsigned v;
        do {
            asm volatile("ld.global.acquire.gpu.u32 %0, [%1];"
                         : "=r"(v) : "l"(&g_flags[threadIdx.x * 32]) : "memory");
        } while (v < (unsigned)target);
    }
    __syncthreads();
}

// ---------------- persistent recurrence (tf32 tensor-core dot) -------------------
// 128 CTAs x 256 threads; grid tiled 4 batch-groups x 32 column-groups.
// CTA owns 16 batches x 16 columns (N = 3 gates x 16 = 48 = 6 n8 tiles, M = 16
// = 1 m-tile). Per-CTA h read = 32 KB/step. Warp = 64-k slice: 8 k-steps x
// 6 n-tiles = 48 mma; weight fragments register-resident (96 regs).
// h staged to smem (pitch 24) via cp.async, 2 x 32-k chunks per warp.
// Also writes tf32(h) to g_xc (next layer's A).
#define HTP  24
#define REDP 52
#define SMEM_FLOATS (HH * HTP + 8 * 16 * REDP)

__global__ __launch_bounds__(256) void gru_recurrence(
    const float* __restrict__ whr, const float* __restrict__ whz,
    const float* __restrict__ whn,
    const float* __restrict__ bhr, const float* __restrict__ bhz,
    const float* __restrict__ bhn,
    float* __restrict__ seq,          // [T,B,H]
    float* __restrict__ finals)       // [B,H]
{
    extern __shared__ float sm[];
    float* ht  = sm;                          // [512][HTP] h slice (k-major, tf32 bits)
    float* red = sm + HH * HTP;               // [8][16][REDP] partials

    const int tid = threadIdx.x;
    const int w   = tid >> 5;                 // warp = 64-k slice (0..7)
    const int lane = tid & 31;
    const int r  = lane >> 2;                 // fragment row group
    const int cq = lane & 3;                  // fragment col group
    const int bg    = blockIdx.x >> 5;        // batch group (0..3)
    const int bbase = bg * 16;
    const int jbase = (blockIdx.x & 31) * 16; // column group

    // activation-phase identity: 256 threads = 16 batches x 16 cols
    const int ab = tid >> 4;                  // local batch 0..15
    const int aj = tid & 15;                  // local col 0..15
    const int jglob = jbase + aj;

    // ---- load W fragments (once, resident all 512 steps) ----
    uint32_t bw[8][6][2];
#pragma unroll
    for (int ks = 0; ks < 8; ks++)
#pragma unroll
        for (int nt = 0; nt < 6; nt++)
#pragma unroll
            for (int e = 0; e < 2; e++) {
                const int g  = nt >> 1;
                const int jh = nt & 1;
                const int k = (w << 6) + ks * 8 + cq + e * 4;
                const float* src = (g == 0) ? whr : ((g == 1) ? whz : whn);
                bw[ks][nt][e] =
                    __float_as_uint(tf32r(src[(size_t)k * HH + jbase + jh * 8 + r]));
            }
    const float bh_r = bhr[jglob];
    const float bh_z = bhz[jglob];
    const float bh_n = bhn[jglob];
    __syncthreads();

    const uint32_t ht_u32 = (uint32_t)__cvta_generic_to_shared(ht);

    // warp chunk (32 k rows x 16 batches = 128 float4): lane does 4
#define ISSUE_CHUNK(cc)                                                          \
    {                                                                            \
        _Pragma("unroll")                                                        \
        for (int i = 0; i < 4; i++) {                                            \
            const int id = i * 32 + lane;                                        \
            const int row = (w << 6) + (cc) * 32 + (id >> 2);                    \
            const int col4 = id & 3;                                             \
            cpa16(ht_u32 + (uint32_t)(row * HTP + col4 * 4) * 4u,                \
                  src4 + row * 16 + bg * 4 + col4);                              \
        }                                                                        \
        CP_COMMIT();                                                             \
    }

    for (int t = 0; t < TT; t++) {
        // prefetch gate-x (hidden under dot)
        const int gi = (t * BB + bbase + ab) * HH + jglob;
        const float gxr = __ldcs(&g_gx[0][gi]);
        const float gxz = __ldcs(&g_gx[1][gi]);
        const float gxn = __ldcs(&g_gx[2][gi]);

        const float4* src4 = (const float4*)g_ht[(t - 1) & 1];

        float cacc[6][4];
#pragma unroll
        for (int nt = 0; nt < 6; nt++)
#pragma unroll
            for (int i = 0; i < 4; i++) cacc[nt][i] = 0.f;

        ISSUE_CHUNK(0)
        ISSUE_CHUNK(1)

#pragma unroll
        for (int c = 0; c < 2; c++) {
            if (c == 0) CP_WAIT_1(); else CP_WAIT_0();
            __syncwarp();

#pragma unroll
            for (int ks2 = 0; ks2 < 4; ks2++) {
                const int ks = c * 4 + ks2;
                const int kb = (w << 6) + ks * 8;
                uint32_t a[4];
                const int base = (kb + cq) * HTP + r;
                a[0] = __float_as_uint(ht[base]);
                a[1] = __float_as_uint(ht[base + 8]);
                a[2] = __float_as_uint(ht[base + 4 * HTP]);
                a[3] = __float_as_uint(ht[base + 4 * HTP + 8]);
#pragma unroll
                for (int nt = 0; nt < 6; nt++)
                    mma_tf32(cacc[nt], a, bw[ks][nt]);
            }
        }

        // store partials: red[w][b][n], n = nt*8 + 2*cq (+1); b rows r, r+8
        {
            float* rb = red + w * (16 * REDP);
#pragma unroll
            for (int nt = 0; nt < 6; nt++) {
                const int n0 = nt * 8 + 2 * cq;
                *(float2*)&rb[r * REDP + n0] =
                    make_float2(cacc[nt][0], cacc[nt][1]);
                *(float2*)&rb[(r + 8) * REDP + n0] =
                    make_float2(cacc[nt][2], cacc[nt][3]);
            }
        }
        __syncthreads();

        // ---- reduce over 8 warps + activation (thread = (ab, aj)) ----
        float ar = bh_r, az = bh_z, an = bh_n;
#pragma unroll
        for (int ww = 0; ww < 8; ww++) {
            const float* rb = red + ww * (16 * REDP) + ab * REDP;
            ar += rb[aj];
            az += rb[16 + aj];
            an += rb[32 + aj];
        }

        const float rg = 1.f / (1.f + __expf(-(gxr + ar)));
        const float zg = 1.f / (1.f + __expf(-(gxz + az)));
        const float ng = tanhf(gxn + rg * an);
        const float hp = ht[jglob * HTP + ab];          // h_prev from smem stage
        const float hn_ = (1.f - zg) * ng + zg * hp;

        const float hq = tf32r(hn_);
        __stcg(&g_ht[t & 1][jglob * BB + bbase + ab], hq);
        __stcg(&g_xc[gi], hq);                          // next layer's A (tf32)
        seq[gi] = hn_;
        if (t == TT - 1) finals[(size_t)(bbase + ab) * HH + jglob] = hn_;

        grid_sync_flags(t + 1);
    }
#undef ISSUE_CHUNK
}

// -------------------------------- launch -----------------------------------------
extern "C" void kernel_launch(void* const* d_in, const int* in_sizes, int n_in,
                              void* d_out, int out_size) {
    const float* x    = (const float*)d_in[0];
    const float* init = (const float*)d_in[1];
    const float* w_ir = (const float*)d_in[2];
    const float* w_hr = (const float*)d_in[3];
    const float* w_iz = (const float*)d_in[4];
    const float* w_hz = (const float*)d_in[5];
    const float* w_in = (const float*)d_in[6];
    const float* w_hn = (const float*)d_in[7];
    const float* b_ir = (const float*)d_in[8];
    const float* b_hr = (const float*)d_in[9];
    const float* b_iz = (const float*)d_in[10];
    const float* b_hz = (const float*)d_in[11];
    const float* b_in = (const float*)d_in[12];
    const float* b_hn = (const float*)d_in[13];

    float* out    = (float*)d_out;
    float* seq    = out;                          // [T,B,H]
    float* finals = out + (size_t)TT * BB * HH;   // [L,B,H]

    const size_t rec_smem = (size_t)SMEM_FLOATS * sizeof(float);
    cudaFuncSetAttribute(gru_recurrence,
                         cudaFuncAttributeMaxDynamicSharedMemorySize,
                         (int)rec_smem);
    const size_t gemm_smem = (size_t)GEMM_SMEM_FLOATS * sizeof(float);
    cudaFuncSetAttribute(gemm_xw_mma,
                         cudaFuncAttributeMaxDynamicSharedMemorySize,
                         (int)gemm_smem);

    dim3 ggrid(TT * BB / 128, HH / 128, 3);       // 256 x 4 x 3

    conv_x<<<TT * BB * HH / 1024, 256>>>(x);             // layer-0 A (tf32)
    conv_w<<<LL * 3 * HH * HH / 1024, 256>>>(w_ir, w_iz, w_in);  // both layers

    for (int l = 0; l < LL; l++) {
        const size_t wo = (size_t)l * HH * HH;
        const size_t bo = (size_t)l * HH;

        gemm_xw_mma<<<ggrid, 256, gemm_smem>>>(l, b_ir + bo, b_iz + bo, b_in + bo);

        transpose_h0<<<HH * BB / 256, 256>>>(init + (size_t)l * BB * HH);

        gru_recurrence<<<NBLK, 256, rec_smem>>>(
            w_hr + wo, w_hz + wo, w_hn + wo,
            b_hr + bo, b_hz + bo, b_hn + bo,
            seq,
            finals + (size_t)l * BB * HH);
    }
}

// round 17
// speedup vs baseline: 1.2047x; 1.0892x over previous
#include <cuda_runtime.h>
#include <cuda_bf16.h>
#include <math.h>
#include <stdint.h>

#define TT   512
#define BB   64
#define HH   512
#define LL   2
#define NBLK 128          // recurrence grid (1 CTA/SM, all co-resident)

typedef unsigned long long ull;

// ---------------- scratch (__device__ globals; allocation-free) ----------------
__device__ float g_gx[3][TT * BB * HH];     // gate-x planes (r,z,n) for current layer
__device__ float g_xc[TT * BB * HH];        // tf32-rounded A for current layer GEMM
__device__ float g_wc[LL][3][HH * HH];      // tf32-rounded input weights (both layers)
// hidden state, batch-group-blocked: [buf][bg][k][16]  (tf32-rounded)
__device__ float g_ht[2][4 * HH * 16];
__device__ unsigned int g_flags[NBLK * 32]; // per-CTA barrier flags, 128B stride

// tf32 round-to-nearest of an fp32 (bits usable by mma.tf32)
__device__ __forceinline__ float tf32r(float x) {
    uint32_t y;
    asm("cvt.rna.tf32.f32 %0, %1;" : "=r"(y) : "f"(x));
    return __uint_as_float(y);
}

__device__ __forceinline__ void mma_tf32(float c[4], const uint32_t a[4],
                                         const uint32_t b[2]) {
    asm volatile(
        "mma.sync.aligned.m16n8k8.row.col.f32.tf32.tf32.f32 "
        "{%0,%1,%2,%3}, {%4,%5,%6,%7}, {%8,%9}, {%0,%1,%2,%3};"
        : "+f"(c[0]), "+f"(c[1]), "+f"(c[2]), "+f"(c[3])
        : "r"(a[0]), "r"(a[1]), "r"(a[2]), "r"(a[3]), "r"(b[0]), "r"(b[1]));
}

// cp.async 16B (L2-cached) + group control (GEMM only)
__device__ __forceinline__ void cpa16(uint32_t smem, const void* g) {
    asm volatile("cp.async.cg.shared.global [%0], [%1], 16;"
                 :: "r"(smem), "l"(g) : "memory");
}
#define CP_COMMIT()  asm volatile("cp.async.commit_group;" ::: "memory")
#define CP_WAIT_1()  asm volatile("cp.async.wait_group 1;" ::: "memory")
#define CP_WAIT_0()  asm volatile("cp.async.wait_group 0;" ::: "memory")

// ---- bulk copy + mbarrier (recurrence staging) ----
__device__ __forceinline__ void mbar_init(uint32_t mbar, unsigned count) {
    asm volatile("mbarrier.init.shared.b64 [%0], %1;" :: "r"(mbar), "r"(count)
                 : "memory");
}
__device__ __forceinline__ void mbar_arrive_tx(uint32_t mbar, unsigned bytes) {
    asm volatile("mbarrier.arrive.expect_tx.shared.b64 _, [%0], %1;"
                 :: "r"(mbar), "r"(bytes) : "memory");
}
__device__ __forceinline__ void bulk_g2s(uint32_t smem, const void* g,
                                         unsigned bytes, uint32_t mbar) {
    asm volatile("cp.async.bulk.shared::cta.global.mbarrier::complete_tx::bytes "
                 "[%0], [%1], %2, [%3];"
                 :: "r"(smem), "l"(g), "r"(bytes), "r"(mbar) : "memory");
}
__device__ __forceinline__ void mbar_wait(uint32_t mbar, unsigned parity) {
    asm volatile(
        "{\n\t"
        ".reg .pred P;\n\t"
        "WL%=:\n\t"
        "mbarrier.try_wait.parity.acquire.cta.shared::cta.b64 P, [%0], %1, 0x989680;\n\t"
        "@P bra WD%=;\n\t"
        "bra WL%=;\n\t"
        "WD%=:\n\t"
        "}"
        :: "r"(mbar), "r"(parity) : "memory");
}

// ---------------- operand pre-conversion ------------------------------------------
__global__ __launch_bounds__(256) void conv_x(const float* __restrict__ x) {
    const int i = blockIdx.x * 256 + threadIdx.x;     // float4 index
    float4 v = *(const float4*)(x + (size_t)i * 4);
    v.x = tf32r(v.x); v.y = tf32r(v.y); v.z = tf32r(v.z); v.w = tf32r(v.w);
    *(float4*)(g_xc + (size_t)i * 4) = v;
}

// both layers, all 3 gates in one launch (6 matrices)
__global__ __launch_bounds__(256) void conv_w(const float* __restrict__ w0,
                                              const float* __restrict__ w1,
                                              const float* __restrict__ w2) {
    const int i = blockIdx.x * 256 + threadIdx.x;     // float4 index, < 393216
    const int m = i >> 16;                            // 0..5
    const int layer = (m >= 3) ? 1 : 0;
    const int gate  = m - layer * 3;
    const int rem = i & 65535;
    const float* base = (gate == 0) ? w0 : ((gate == 1) ? w1 : w2);
    const float* src = base + (size_t)layer * HH * HH;
    float4 v = *(const float4*)(src + (size_t)rem * 4);
    v.x = tf32r(v.x); v.y = tf32r(v.y); v.z = tf32r(v.z); v.w = tf32r(v.w);
    *(float4*)(g_wc[layer][gate] + (size_t)rem * 4) = v;
}

// ---------------- h0 transpose (blocked layout) + barrier-flag reset --------------
__global__ __launch_bounds__(256) void transpose_h0(const float* __restrict__ h0) {
    const int i = blockIdx.x * 256 + threadIdx.x;   // 0..32767
    const int k = i >> 6;
    const int b = i & 63;
    g_ht[1][(b >> 4) * (HH * 16) + k * 16 + (b & 15)] = tf32r(h0[(size_t)b * HH + k]);
    if (i < NBLK) g_flags[i * 32] = 0;              // reset barrier flags per layer
}

// ---------------- input GEMM (tensor cores, tf32, cp.async 3-stage) ---------------
#define APITCH 36
#define BPITCH 136
#define A_STG (128 * APITCH)                 // 4608 floats
#define B_STG (32 * BPITCH)                  // 4352 floats
#define GEMM_SMEM_FLOATS (3 * A_STG + 3 * B_STG)

__global__ __launch_bounds__(256) void gemm_xw_mma(int layer,
                                                   const float* __restrict__ bias0,
                                                   const float* __restrict__ bias1,
                                                   const float* __restrict__ bias2) {
    extern __shared__ float gsm[];
    const int gate = blockIdx.z;
    const float* A    = g_xc;
    const float* W    = g_wc[layer][gate];
    const float* bias = (gate == 0) ? bias0 : ((gate == 1) ? bias1 : bias2);

    const int bm = blockIdx.x * 128;
    const int bn = blockIdx.y * 128;
    const int tid = threadIdx.x;
    const int lane = tid & 31;
    const int wid = tid >> 5;
    const int warp_m = wid >> 2;              // 0..1
    const int warp_n = wid & 3;               // 0..3

    const uint32_t sm_u32 = (uint32_t)__cvta_generic_to_shared(gsm);

    float acc[4][4][4];
#pragma unroll
    for (int mt = 0; mt < 4; mt++)
#pragma unroll
        for (int nt = 0; nt < 4; nt++)
#pragma unroll
            for (int i = 0; i < 4; i++) acc[mt][nt][i] = 0.f;

#define GSTAGE(s, kt32)                                                          \
    {                                                                            \
        _Pragma("unroll")                                                        \
        for (int i = 0; i < 4; i++) {                                            \
            const int idx = i * 256 + tid;                                       \
            const int arow = idx >> 3;                                           \
            const int kq = idx & 7;                                              \
            cpa16(sm_u32 + (uint32_t)((s) * A_STG + arow * APITCH + kq * 4) * 4u,\
                  A + (size_t)(bm + arow) * HH + (kt32) + kq * 4);               \
        }                                                                        \
        _Pragma("unroll")                                                        \
        for (int i = 0; i < 4; i++) {                                            \
            const int idx = i * 256 + tid;                                       \
            const int krow = idx >> 5;                                           \
            const int nq = idx & 31;                                             \
            cpa16(sm_u32 + (uint32_t)(3 * A_STG + (s) * B_STG + krow * BPITCH    \
                                      + nq * 4) * 4u,                            \
                  W + (size_t)((kt32) + krow) * HH + bn + nq * 4);               \
        }                                                                        \
        CP_COMMIT();                                                             \
    }

    GSTAGE(0, 0)
    GSTAGE(1, 32)

    const int r = lane >> 2;
    const int cq = lane & 3;
    const int mrow = warp_m * 64 + r;
    const int nbase = warp_n * 32 + r;

    for (int it = 0; it < 16; it++) {
        const int kt = it * 32;
        if (kt == 480) { CP_WAIT_0(); } else { CP_WAIT_1(); }
        __syncthreads();
        if (kt + 64 < HH) GSTAGE((it + 2) % 3, kt + 64)

        const float* Ab = gsm + (it % 3) * A_STG;
        const float* Bb = gsm + 3 * A_STG + (it % 3) * B_STG;

#pragma unroll
        for (int ks = 0; ks < 4; ks++) {
            const int kk = ks * 8;
            uint32_t af[4][4];
#pragma unroll
            for (int mt = 0; mt < 4; mt++) {
                const int mr = mrow + mt * 16;
                af[mt][0] = __float_as_uint(Ab[mr * APITCH + kk + cq]);
                af[mt][1] = __float_as_uint(Ab[(mr + 8) * APITCH + kk + cq]);
                af[mt][2] = __float_as_uint(Ab[mr * APITCH + kk + cq + 4]);
                af[mt][3] = __float_as_uint(Ab[(mr + 8) * APITCH + kk + cq + 4]);
            }
            uint32_t bf[4][2];
#pragma unroll
            for (int nt = 0; nt < 4; nt++) {
                bf[nt][0] = __float_as_uint(Bb[(kk + cq) * BPITCH + nbase + nt * 8]);
                bf[nt][1] = __float_as_uint(Bb[(kk + cq + 4) * BPITCH + nbase + nt * 8]);
            }
#pragma unroll
            for (int mt = 0; mt < 4; mt++)
#pragma unroll
                for (int nt = 0; nt < 4; nt++)
                    mma_tf32(acc[mt][nt], af[mt], bf[nt]);
        }
    }

    // epilogue
    float* C = g_gx[0] + (size_t)gate * ((size_t)TT * BB * HH);
    const int m0 = bm + warp_m * 64 + r;
    const int n0 = bn + warp_n * 32 + 2 * cq;
#pragma unroll
    for (int nt = 0; nt < 4; nt++) {
        const int col = n0 + nt * 8;
        const float b0 = bias[col];
        const float b1 = bias[col + 1];
#pragma unroll
        for (int mt = 0; mt < 4; mt++) {
            const int row0 = m0 + mt * 16;
            float2 v0 = make_float2(acc[mt][nt][0] + b0, acc[mt][nt][1] + b1);
            float2 v1 = make_float2(acc[mt][nt][2] + b0, acc[mt][nt][3] + b1);
            *(float2*)&C[(size_t)row0 * HH + col] = v0;
            *(float2*)&C[(size_t)(row0 + 8) * HH + col] = v1;
        }
    }
#undef GSTAGE
}

// ---------------- flag-based grid barrier ----------------------------------------
__device__ __forceinline__ void grid_sync_flags(int target) {
    __syncthreads();
    if (threadIdx.x == 0) {
        asm volatile("st.global.release.gpu.u32 [%0], %1;"
                     :: "l"(&g_flags[blockIdx.x * 32]), "r"((unsigned)target)
                     : "memory");
    }
    if (threadIdx.x < NBLK) {
        unsigned v;
        do {
            asm volatile("ld.global.acquire.gpu.u32 %0, [%1];"
                         : "=r"(v) : "l"(&g_flags[threadIdx.x * 32]) : "memory");
        } while (v < (unsigned)target);
    }
    __syncthreads();
}

// ---------------- persistent recurrence (tf32 mma, bulk-copy staging) -------------
// 128 CTAs x 256 threads; grid tiled 4 batch-groups x 32 column-groups.
// CTA owns 16 batches x 16 columns. Warp = 64-k slice: 8 k-steps x 6 n-tiles.
// h is batch-group-blocked in gmem ([bg][k][16], contiguous 32 KB per CTA), so
// each warp stages its 64-k slice as 2 x 2KB cp.async.bulk (one UBLKCP each,
// mbarrier complete_tx) instead of 256 x 16B cp.async -> staging issue cost
// collapses. smem h is packed pitch 16 (2-way-conflicted A gathers, accepted).
#define HTP  16
#define REDP 52
#define HT_FLOATS (HH * HTP)                      // 8192
#define RED_FLOATS (8 * 16 * REDP)                // 6656
#define SMEM_FLOATS (HT_FLOATS + RED_FLOATS + 40) // + 16 mbars (128B) + pad

__global__ __launch_bounds__(256) void gru_recurrence(
    const float* __restrict__ whr, const float* __restrict__ whz,
    const float* __restrict__ whn,
    const float* __restrict__ bhr, const float* __restrict__ bhz,
    const float* __restrict__ bhn,
    float* __restrict__ seq,          // [T,B,H]
    float* __restrict__ finals)       // [B,H]
{
    extern __shared__ float sm[];
    float* ht  = sm;                               // [512][16] h slice (tf32 bits)
    float* red = sm + HT_FLOATS;                   // [8][16][REDP] partials
    // 16 mbarriers (8 warps x 2 chunks), 8B each, after red (8B aligned)
    const uint32_t smem_base = (uint32_t)__cvta_generic_to_shared(sm);
    const uint32_t mbar_base = smem_base + (uint32_t)(HT_FLOATS + RED_FLOATS) * 4u;

    const int tid = threadIdx.x;
    const int w   = tid >> 5;                 // warp = 64-k slice (0..7)
    const int lane = tid & 31;
    const int r  = lane >> 2;                 // fragment row group
    const int cq = lane & 3;                  // fragment col group
    const int bg    = blockIdx.x >> 5;        // batch group (0..3)
    const int bbase = bg * 16;
    const int jbase = (blockIdx.x & 31) * 16; // column group

    // activation-phase identity: 256 threads = 16 batches x 16 cols
    const int ab = tid >> 4;                  // local batch 0..15
    const int aj = tid & 15;                  // local col 0..15
    const int jglob = jbase + aj;

    // ---- init mbarriers (count = 1: elected lane arrives via expect_tx) ----
    if (tid < 16) mbar_init(mbar_base + tid * 8, 1);

    // ---- load W fragments (once, resident all 512 steps) ----
    uint32_t bw[8][6][2];
#pragma unroll
    for (int ks = 0; ks < 8; ks++)
#pragma unroll
        for (int nt = 0; nt < 6; nt++)
#pragma unroll
            for (int e = 0; e < 2; e++) {
                const int g  = nt >> 1;
                const int jh = nt & 1;
                const int k = (w << 6) + ks * 8 + cq + e * 4;
                const float* src = (g == 0) ? whr : ((g == 1) ? whz : whn);
                bw[ks][nt][e] =
                    __float_as_uint(tf32r(src[(size_t)k * HH + jbase + jh * 8 + r]));
            }
    const float bh_r = bhr[jglob];
    const float bh_z = bhz[jglob];
    const float bh_n = bhn[jglob];
    __syncthreads();                          // mbar init + weights visible

    const uint32_t mbA = mbar_base + (w * 2 + 0) * 8;
    const uint32_t mbB = mbar_base + (w * 2 + 1) * 8;
    const uint32_t ht_w = smem_base + (uint32_t)(w * 64 * HTP) * 4u; // warp slice

    for (int t = 0; t < TT; t++) {
        // prefetch gate-x (hidden under dot)
        const int gi = (t * BB + bbase + ab) * HH + jglob;
        const float gxr = __ldcs(&g_gx[0][gi]);
        const float gxz = __ldcs(&g_gx[1][gi]);
        const float gxn = __ldcs(&g_gx[2][gi]);

        // stage this warp's 64-k slice: 2 x 2KB bulk copies
        const float* src = g_ht[(t - 1) & 1] + bg * (HH * 16) + (w * 64) * 16;
        if (lane == 0) {
            mbar_arrive_tx(mbA, 2048);
            bulk_g2s(ht_w, src, 2048, mbA);
            mbar_arrive_tx(mbB, 2048);
            bulk_g2s(ht_w + 2048, src + 512, 2048, mbB);
        }

        float cacc[6][4];
#pragma unroll
        for (int nt = 0; nt < 6; nt++)
#pragma unroll
            for (int i = 0; i < 4; i++) cacc[nt][i] = 0.f;

        const unsigned par = (unsigned)(t & 1);
#pragma unroll
        for (int c = 0; c < 2; c++) {
            mbar_wait(c == 0 ? mbA : mbB, par);

#pragma unroll
            for (int ks2 = 0; ks2 < 4; ks2++) {
                const int ks = c * 4 + ks2;
                const int kb = (w << 6) + ks * 8;
                uint32_t a[4];
                const int base = (kb + cq) * HTP + r;
                a[0] = __float_as_uint(ht[base]);
                a[1] = __float_as_uint(ht[base + 8]);
                a[2] = __float_as_uint(ht[base + 4 * HTP]);
                a[3] = __float_as_uint(ht[base + 4 * HTP + 8]);
#pragma unroll
                for (int nt = 0; nt < 6; nt++)
                    mma_tf32(cacc[nt], a, bw[ks][nt]);
            }
        }

        // store partials: red[w][b][n]
        {
            float* rb = red + w * (16 * REDP);
#pragma unroll
            for (int nt = 0; nt < 6; nt++) {
                const int n0 = nt * 8 + 2 * cq;
                *(float2*)&rb[r * REDP + n0] =
                    make_float2(cacc[nt][0], cacc[nt][1]);
                *(float2*)&rb[(r + 8) * REDP + n0] =
                    make_float2(cacc[nt][2], cacc[nt][3]);
            }
        }
        __syncthreads();

        // ---- reduce over 8 warps + activation (thread = (ab, aj)) ----
        float ar = bh_r, az = bh_z, an = bh_n;
#pragma unroll
        for (int ww = 0; ww < 8; ww++) {
            const float* rb = red + ww * (16 * REDP) + ab * REDP;
            ar += rb[aj];
            az += rb[16 + aj];
            an += rb[32 + aj];
        }

        const float rg = 1.f / (1.f + __expf(-(gxr + ar)));
        const float zg = 1.f / (1.f + __expf(-(gxz + az)));
        const float ng = tanhf(gxn + rg * an);
        const float hp = ht[jglob * HTP + ab];          // h_prev from smem stage
        const float hn_ = (1.f - zg) * ng + zg * hp;

        const float hq = tf32r(hn_);
        __stcg(&g_ht[t & 1][bg * (HH * 16) + jglob * 16 + ab], hq);
        __stcg(&g_xc[gi], hq);                          // next layer's A (tf32)
        seq[gi] = hn_;
        if (t == TT - 1) finals[(size_t)(bbase + ab) * HH + jglob] = hn_;

        grid_sync_flags(t + 1);
    }
}

// -------------------------------- launch -----------------------------------------
extern "C" void kernel_launch(void* const* d_in, const int* in_sizes, int n_in,
                              void* d_out, int out_size) {
    const float* x    = (const float*)d_in[0];
    const float* init = (const float*)d_in[1];
    const float* w_ir = (const float*)d_in[2];
    const float* w_hr = (const float*)d_in[3];
    const float* w_iz = (const float*)d_in[4];
    const float* w_hz = (const float*)d_in[5];
    const float* w_in = (const float*)d_in[6];
    const float* w_hn = (const float*)d_in[7];
    const float* b_ir = (const float*)d_in[8];
    const float* b_hr = (const float*)d_in[9];
    const float* b_iz = (const float*)d_in[10];
    const float* b_hz = (const float*)d_in[11];
    const float* b_in = (const float*)d_in[12];
    const float* b_hn = (const float*)d_in[13];

    float* out    = (float*)d_out;
    float* seq    = out;                          // [T,B,H]
    float* finals = out + (size_t)TT * BB * HH;   // [L,B,H]

    const size_t rec_smem = (size_t)SMEM_FLOATS * sizeof(float);
    cudaFuncSetAttribute(gru_recurrence,
                         cudaFuncAttributeMaxDynamicSharedMemorySize,
                         (int)rec_smem);
    const size_t gemm_smem = (size_t)GEMM_SMEM_FLOATS * sizeof(float);
    cudaFuncSetAttribute(gemm_xw_mma,
                         cudaFuncAttributeMaxDynamicSharedMemorySize,
                         (int)gemm_smem);

    dim3 ggrid(TT * BB / 128, HH / 128, 3);       // 256 x 4 x 3

    conv_x<<<TT * BB * HH / 1024, 256>>>(x);             // layer-0 A (tf32)
    conv_w<<<LL * 3 * HH * HH / 1024, 256>>>(w_ir, w_iz, w_in);  // both layers

    for (int l = 0; l < LL; l++) {
        const size_t wo = (size_t)l * HH * HH;
        const size_t bo = (size_t)l * HH;

        gemm_xw_mma<<<ggrid, 256, gemm_smem>>>(l, b_ir + bo, b_iz + bo, b_in + bo);

        transpose_h0<<<HH * BB / 256, 256>>>(init + (size_t)l * BB * HH);

        gru_recurrence<<<NBLK, 256, rec_smem>>>(
            w_hr + wo, w_hz + wo, w_hn + wo,
            b_hr + bo, b_hz + bo, b_hn + bo,
            seq,
            finals + (size_t)l * BB * HH);
    }
}